// round 16
// baseline (speedup 1.0000x reference)
#include <cuda_runtime.h>
#include <cuda_fp16.h>
#include <cstdint>

// TwoBranchDH_SFNN, R11: T-split (2 segments) with linear state correction.
// k1 basis:  P[j= comp*512+h][Dlt-1], comp0=alpha^D, comp1/2=wo(1-a)*S_beta(D)
// k2 main:   grid 1024 = seg(2) x quarter(4) x batch(128); 128 thr; 64 stages
//            of 16 t; R10 HMMA structure; fp16 dots+y; seg0 saves states.
// k3 corr:   GEMM [B,1536]x[1536,1024] -> g_corr (correction for t>=1024)
// k4 epi:    out = sigmoid(sum_q g_part + corr + bo)

namespace {

constexpr int B_SZ  = 128;
constexpr int T_SZ  = 2048;
constexpr int T_SEG = 1024;
constexpr int DIN   = 40;
constexpr int KHALF = 20;
constexpr int THREADS = 128;
constexpr int ST      = 16;
constexpr int NSTAGES = T_SEG / ST;     // 64

// smem (u32 words)
constexpr int RW    = 136;              // dot row stride (u32)
constexpr int BRH   = 8 * RW;           // per-branch block = 1088
constexpr int DOTH  = 2 * BRH;          // one dot buffer = 2176
constexpr int YWH   = 136;              // y row stride (halves)
constexpr int YTOTH = ST * YWH;         // one y buffer (halves) = 2176
constexpr int XWH   = ST * 64;          // x buffer (halves) = 1024
constexpr int SMEM_BYTES = (2 * DOTH) * 4 + (2 * YTOTH) * 2 + (2 * XWH) * 2; // 30208

typedef unsigned long long u64;
typedef uint32_t u32;

__device__ float g_part[4 * B_SZ * T_SZ];        // partial channel sums
__device__ float g_d1s[B_SZ * 512];              // seg0 boundary states
__device__ float g_d2s[B_SZ * 512];
__device__ float g_yms[B_SZ * 512];              // wo*mem at boundary
__device__ float g_P[1536 * 1024];               // correction basis
__device__ float g_corr[B_SZ * 1024];            // per-(b,t>=1024) correction

__device__ __forceinline__ u32 smem_u32(const void* p) {
    u32 a;
    asm("{ .reg .u64 t; cvta.to.shared.u64 t, %1; cvt.u32.u64 %0, t; }"
        : "=r"(a) : "l"(p));
    return a;
}
__device__ __forceinline__ u64 pkf(float lo, float hi) {
    u64 r; asm("mov.b64 %0, {%1, %2};" : "=l"(r) : "f"(lo), "f"(hi)); return r;
}
__device__ __forceinline__ float2 unpk(u64 v) {
    float2 r; asm("mov.b64 {%0, %1}, %2;" : "=f"(r.x), "=f"(r.y) : "l"(v)); return r;
}
__device__ __forceinline__ u64 fma2(u64 a, u64 b, u64 c) {
    u64 d; asm("fma.rn.f32x2 %0, %1, %2, %3;" : "=l"(d) : "l"(a), "l"(b), "l"(c)); return d;
}
__device__ __forceinline__ void ldmat4(u32* r, u32 addr) {
    asm volatile("ldmatrix.sync.aligned.m8n8.x4.shared.b16 {%0,%1,%2,%3}, [%4];"
                 : "=r"(r[0]), "=r"(r[1]), "=r"(r[2]), "=r"(r[3]) : "r"(addr));
}
__device__ __forceinline__ void mma16816(float& d0, float& d1, float& d2, float& d3,
                                         const u32* a, u32 b0, u32 b1) {
    asm volatile("mma.sync.aligned.m16n8k16.row.col.f32.f16.f16.f32 "
                 "{%0,%1,%2,%3}, {%4,%5,%6,%7}, {%8,%9}, {%0,%1,%2,%3};"
                 : "+f"(d0), "+f"(d1), "+f"(d2), "+f"(d3)
                 : "r"(a[0]), "r"(a[1]), "r"(a[2]), "r"(a[3]), "r"(b0), "r"(b1));
}
__device__ __forceinline__ float sigf(float v) { return 1.0f / (1.0f + expf(-v)); }
__device__ __forceinline__ u32 packh(float a, float b) {
    __half2 h = __floats2half2_rn(a, b);
    return *reinterpret_cast<u32*>(&h);
}

// ===================== k1: correction basis =====================
__global__ void sfnn_basis(const float* __restrict__ Wo,
                           const float* __restrict__ tau_m,
                           const float* __restrict__ tau_n1,
                           const float* __restrict__ tau_n2) {
    const int gid = blockIdx.x * blockDim.x + threadIdx.x;   // < 24576
    if (gid >= 1536 * 16) return;
    const int chunk = gid & 15;
    const int j     = gid >> 4;          // 0..1535
    const int h     = j & 511;
    const int comp  = j >> 9;            // 0,1,2
    const float al = sigf(tau_m[h]);
    const float wo = Wo[h];
    const float bt = (comp == 1) ? sigf(tau_n1[h]) : sigf(tau_n2[h]);
    const int d0 = chunk * 64 + 1;       // Delta start
    float pa = exp2f((float)d0 * log2f(al));
    float pb = exp2f((float)d0 * log2f(bt));
    const float delta = bt - al;
    const bool exact = fabsf(delta) > 1e-5f;
    const float coef = wo * (1.f - al);
    float* Prow = g_P + (size_t)j * 1024 + (d0 - 1);
#pragma unroll 4
    for (int i = 0; i < 64; i++) {
        float val;
        if (comp == 0) {
            val = pa;                                    // alpha^Delta (c = wo*mem0)
        } else {
            const float S = exact ? bt * (pb - pa) / delta
                                  : (float)(d0 + i) * pa;
            val = coef * S;
        }
        Prow[i] = val;
        pa *= al; pb *= bt;
    }
}

// ===================== k2: main =====================
__global__ void __launch_bounds__(THREADS, 7)
sfnn_r11_kernel(const float* __restrict__ x,
                const float* __restrict__ W1, const float* __restrict__ b1,
                const float* __restrict__ W2, const float* __restrict__ b2,
                const float* __restrict__ Wo, const float* __restrict__ tau_m,
                const float* __restrict__ tau_n1, const float* __restrict__ tau_n2) {
    extern __shared__ __align__(16) u32 smw[];
    u32*    dotw = smw;                                        // 2*DOTH u32
    __half* yh   = reinterpret_cast<__half*>(smw + 2 * DOTH);  // 2*YTOTH halves
    __half* xsm  = reinterpret_cast<__half*>(smw + 2 * DOTH + YTOTH);

    const int tid  = threadIdx.x;
    const int lane = tid & 31;
    const int wid  = tid >> 5;
    const int b    = blockIdx.x & (B_SZ - 1);
    const int q    = (blockIdx.x >> 7) & 3;
    const int seg  = blockIdx.x >> 9;
    const int hb   = q * 128;

    const float* xg = x + (size_t)b * T_SZ * DIN + (size_t)seg * T_SEG * DIN;
    const u32 xbase = smem_u32(xsm);
    float* gp = g_part + ((size_t)q * B_SZ + b) * T_SZ + seg * T_SEG;

    // ---- recurrence constants ----
    const int h = hb + tid;
    const float b1v = sigf(tau_n1[h]), b2v = sigf(tau_n2[h]), av = sigf(tau_m[h]);
    const u64 Bp  = pkf(b1v, b2v);
    const u64 Gp  = pkf(1.f - b1v, 1.f - b2v);
    const u64 GBp = pkf((1.f - b1v) * b1[h], (1.f - b2v) * b2[h]);
    const float wo   = Wo[h];
    const float wamg = wo * (1.f - av);      // ym = av*ym + wamg*(d1+d2)

    // ---- W fragments ----
    const int wbr = wid >> 1;
    const int wb  = (wid & 1) * 64;
    u32 BF[8][2][2];
    {
        const float* Ws = wbr ? W2 : W1;
        const int chl = lane >> 2;
        const int kg  = 2 * (lane & 3);
#pragma unroll
        for (int nt = 0; nt < 8; nt++) {
            const int ch = hb + wb + nt * 8 + chl;
#pragma unroll
            for (int kt = 0; kt < 2; kt++) {
                const int k0 = kt * 16 + kg;
                const float v0 = (k0     < KHALF) ? Ws[ch * KHALF + k0    ] : 0.f;
                const float v1 = (k0 + 1 < KHALF) ? Ws[ch * KHALF + k0 + 1] : 0.f;
                const float v2 = (k0 + 8 < KHALF) ? Ws[ch * KHALF + k0 + 8] : 0.f;
                const float v3 = (k0 + 9 < KHALF) ? Ws[ch * KHALF + k0 + 9] : 0.f;
                BF[nt][kt][0] = packh(v0, v1);
                BF[nt][kt][1] = packh(v2, v3);
            }
        }
    }

    // ---- x slots: 8 per thread ----
    const int xkk  = tid & 63;
    const int xt0  = tid >> 6;
    const int xk   = xkk & 31;
    const bool xok = (xk < KHALF);
    const int xgc  = (xkk >> 5) * KHALF + xk;

    auto stage_x_direct = [&](int s) {
        const float* xs = xg + (size_t)s * (ST * DIN);
        __half* xb = xsm + (s & 1) * XWH;
#pragma unroll
        for (int i = 0; i < 8; i++) {
            const int t = xt0 + 2 * i;
            const float v = xok ? xs[t * DIN + xgc] : 0.f;
            xb[t * 64 + xkk] = __float2half_rn(v);
        }
    };

    const int tlo  = lane >> 2;
    const int chl2 = 2 * (lane & 3);

    auto mma_stage = [&](int s) {
        const int buf = s & 1;
        u32 A[2][4];
#pragma unroll
        for (int kt = 0; kt < 2; kt++) {
            const u32 addr = xbase + (u32)buf * (XWH * 2)
                           + (u32)(lane & 15) * 128
                           + (u32)(wbr * 32 + kt * 16 + ((lane >> 4) << 3)) * 2;
            ldmat4(A[kt], addr);
        }
        u32* dB = dotw + buf * DOTH + wbr * BRH + tlo * RW;
#pragma unroll
        for (int nt = 0; nt < 8; nt++) {
            float d0 = 0.f, d1 = 0.f, d2 = 0.f, d3 = 0.f;
            mma16816(d0, d1, d2, d3, A[0], BF[nt][0][0], BF[nt][0][1]);
            mma16816(d0, d1, d2, d3, A[1], BF[nt][1][0], BF[nt][1][1]);
            *reinterpret_cast<uint2*>(dB + wb + nt * 8 + chl2) =
                make_uint2(packh(d0, d2), packh(d1, d3));
        }
    };

    auto ysum = [&](int s) {
        const __half* yb = yh + (s & 1) * YTOTH;
#pragma unroll
        for (int tt = 0; tt < 4; tt++) {
            const int t = wid * 4 + tt;
            const __half2* yr = reinterpret_cast<const __half2*>(yb + t * YWH);
            const float2 a = __half22float2(yr[lane]);
            const float2 c = __half22float2(yr[lane + 32]);
            float acc = (a.x + a.y) + (c.x + c.y);
#pragma unroll
            for (int off = 16; off; off >>= 1)
                acc += __shfl_xor_sync(0xFFFFFFFFu, acc, off);
            if (lane == 0) gp[s * ST + t] = acc;
        }
    };

    u64 d12 = 0ull;
    float ym = 0.f;

    stage_x_direct(0);
    stage_x_direct(1);
    __syncthreads();
    mma_stage(0);

    for (int s = 0; s < NSTAGES; s++) {
        __syncthreads();

        // early x LDG for s+2 (latency hidden behind the whole body)
        float xr[8];
        const bool dox = (s + 2 < NSTAGES);
        if (dox) {
            const float* xs = xg + (size_t)(s + 2) * (ST * DIN);
#pragma unroll
            for (int i = 0; i < 8; i++)
                xr[i] = xok ? xs[(xt0 + 2 * i) * DIN + xgc] : 0.f;
        }

        if (s > 0) ysum(s - 1);
        if (s + 1 < NSTAGES) mma_stage(s + 1);

        // recurrence(s)
        {
            const u32* dB = dotw + (s & 1) * DOTH;
            __half* yb = yh + (s & 1) * YTOTH;
            float2 f1[8], f2[8];
#pragma unroll
            for (int r = 0; r < 8; r++) {
                const u32 w1 = dB[r * RW + tid];
                const u32 w2 = dB[BRH + r * RW + tid];
                f1[r] = __half22float2(*reinterpret_cast<const __half2*>(&w1));
                f2[r] = __half22float2(*reinterpret_cast<const __half2*>(&w2));
            }
#pragma unroll
            for (int t = 0; t < 8; t++) {
                d12 = fma2(Bp, d12, fma2(Gp, pkf(f1[t].x, f2[t].x), GBp));
                const float2 dd = unpk(d12);
                ym = __fmaf_rn(av, ym, wamg * (dd.x + dd.y));
                yb[t * YWH + tid] = __float2half_rn(ym);
            }
#pragma unroll
            for (int t = 0; t < 8; t++) {
                d12 = fma2(Bp, d12, fma2(Gp, pkf(f1[t].y, f2[t].y), GBp));
                const float2 dd = unpk(d12);
                ym = __fmaf_rn(av, ym, wamg * (dd.x + dd.y));
                yb[(t + 8) * YWH + tid] = __float2half_rn(ym);
            }
        }

        if (dox) {
            __half* xb = xsm + (s & 1) * XWH;
#pragma unroll
            for (int i = 0; i < 8; i++)
                xb[(xt0 + 2 * i) * 64 + xkk] = __float2half_rn(xr[i]);
        }
    }

    __syncthreads();
    ysum(NSTAGES - 1);

    if (seg == 0) {       // save boundary states for correction
        const float2 dd = unpk(d12);
        g_d1s[b * 512 + h] = dd.x;
        g_d2s[b * 512 + h] = dd.y;
        g_yms[b * 512 + h] = ym;
    }
}

// ===================== k3: correction GEMM =====================
__global__ void sfnn_corr() {
    __shared__ float cs[16][132];
    __shared__ float ps[128][68];
    const int tid = threadIdx.x;
    const int tx = tid & 63;
    const int ty = tid >> 6;
    const int dt = blockIdx.x & 15;
    const int db = blockIdx.x >> 4;
    float acc[4] = {0.f, 0.f, 0.f, 0.f};

    for (int kb = 0; kb < 12; kb++) {
#pragma unroll
        for (int i = 0; i < 8; i++) {
            const int idx = tid + i * 256;
            const int bb = idx >> 7, kk = idx & 127;
            const int j = kb * 128 + kk;
            const int comp = j >> 9, hh = j & 511;
            const int bg = db * 16 + bb;
            const float v = (comp == 0) ? g_yms[bg * 512 + hh]
                          : (comp == 1) ? g_d1s[bg * 512 + hh]
                                        : g_d2s[bg * 512 + hh];
            cs[bb][kk] = v;
        }
#pragma unroll
        for (int i = 0; i < 32; i++) {
            const int idx = tid + i * 256;
            const int kk = idx >> 6, dx = idx & 63;
            ps[kk][dx] = g_P[(size_t)(kb * 128 + kk) * 1024 + dt * 64 + dx];
        }
        __syncthreads();
#pragma unroll 4
        for (int kk = 0; kk < 128; kk++) {
            const float p = ps[kk][tx];
#pragma unroll
            for (int i = 0; i < 4; i++)
                acc[i] += cs[ty * 4 + i][kk] * p;
        }
        __syncthreads();
    }
#pragma unroll
    for (int i = 0; i < 4; i++)
        g_corr[(db * 16 + ty * 4 + i) * 1024 + dt * 64 + tx] = acc[i];
}

// ===================== k4: epilogue =====================
__global__ void sfnn_epilogue(const float* __restrict__ bo,
                              float* __restrict__ out) {
    const int i = blockIdx.x * blockDim.x + threadIdx.x;
    if (i < B_SZ * T_SZ) {
        const int N = B_SZ * T_SZ;
        const int b = i >> 11;
        const int t = i & 2047;
        float v = g_part[i] + g_part[N + i] + g_part[2 * N + i]
                + g_part[3 * N + i] + bo[0];
        if (t >= T_SEG) v += g_corr[b * 1024 + (t - T_SEG)];
        out[i] = 1.f / (1.f + __expf(-v));
    }
}

}  // namespace

extern "C" void kernel_launch(void* const* d_in, const int* in_sizes, int n_in,
                              void* d_out, int out_size) {
    const float* x      = (const float*)d_in[0];
    const float* W1     = (const float*)d_in[1];
    const float* b1     = (const float*)d_in[2];
    const float* W2     = (const float*)d_in[3];
    const float* b2     = (const float*)d_in[4];
    const float* Wo     = (const float*)d_in[5];
    const float* bo     = (const float*)d_in[6];
    const float* tau_m  = (const float*)d_in[7];
    const float* tau_n1 = (const float*)d_in[8];
    const float* tau_n2 = (const float*)d_in[9];
    float* out = (float*)d_out;

    sfnn_basis<<<96, 256>>>(Wo, tau_m, tau_n1, tau_n2);

    cudaFuncSetAttribute(sfnn_r11_kernel,
                         cudaFuncAttributeMaxDynamicSharedMemorySize, SMEM_BYTES);
    sfnn_r11_kernel<<<8 * B_SZ, THREADS, SMEM_BYTES>>>(x, W1, b1, W2, b2, Wo,
                                                       tau_m, tau_n1, tau_n2);
    sfnn_corr<<<128, 256>>>();
    sfnn_epilogue<<<(B_SZ * T_SZ + 511) / 512, 512>>>(bo, out);
}